// round 1
// baseline (speedup 1.0000x reference)
#include <cuda_runtime.h>

// Problem constants
#define NB   512      // batches
#define NL   512      // stream length
#define NC   8        // channels
#define NSEG 4        // stream segments (Chen-associative split)
#define SEGLEN 128    // increments per segment (last has 127)
#define SIGSZ 584     // 8 + 64 + 512
#define NINC (NL - 1) // 511

// Scratch for per-segment partial signatures: [batch][seg][584]
__device__ float g_part[(size_t)NB * NSEG * SIGSZ];

// ---------------------------------------------------------------------------
// Segment kernel: each 64-thread group computes the depth-3 signature of one
// (batch, segment). Thread w = i*8+j owns S1[i]/2, S2[i,j], S3[i,j,0..7].
// Per-step update (old S1,S2 on RHS):
//   coeff = dx_i*dx_j/6 + (S1/2)[i]*dx_j + S2[i,j]
//   S3[k] += coeff * dx_k          (8 FMAs, dx_k from two LDS.128)
//   S2    += dx_i*dx_j/2 + S1[i]*dx_j
//   S1/2  += dx_i/2
// No per-step syncs; increments staged to shared in 64-step chunks.
// ---------------------------------------------------------------------------
__global__ __launch_bounds__(128) void seg_kernel(const float* __restrict__ path) {
    __shared__ float sdx[2][64 * NC];   // [task-in-block][step][chan]

    const int tid  = threadIdx.x;
    const int g    = tid >> 6;          // task slot in block (0/1)
    const int w    = tid & 63;          // lane within task
    const int i    = w >> 3;
    const int j    = w & 7;

    const int task  = blockIdx.x * 2 + g;      // 0..2047
    const int batch = task >> 2;               // 0..511
    const int seg   = task & 3;                // 0..3
    const int t0    = seg * SEGLEN;
    const int nsteps = (seg == NSEG - 1) ? (NINC - (NSEG - 1) * SEGLEN) : SEGLEN; // 127 or 128

    const float* __restrict__ pb = path + (size_t)batch * NL * NC;

    float S1h = 0.f;   // S1[i] / 2
    float S2  = 0.f;   // S2[i,j]
    float S3[8];
    #pragma unroll
    for (int k = 0; k < 8; k++) S3[k] = 0.f;

    // Both tasks in a block iterate the chunk loop the same number of times
    // (nsteps is 127 or 128 -> chunk starts {0,64} in both cases), so the
    // __syncthreads below are uniform across the block.
    for (int c0 = 0; c0 < nsteps; c0 += 64) {
        const int Tc = min(64, nsteps - c0);

        __syncthreads();  // protect sdx reuse from previous chunk
        // fill this task's dx chunk: Tc*8 <= 512 elements, 64 threads
        for (int e = w; e < Tc * NC; e += 64) {
            const int t  = e >> 3;
            const int c  = e & 7;
            const int tt = t0 + c0 + t;
            sdx[g][e] = pb[(tt + 1) * NC + c] - pb[tt * NC + c];
        }
        __syncthreads();

        const float* __restrict__ dxp = sdx[g];
        #pragma unroll 4
        for (int t = 0; t < Tc; t++) {
            const float4 d0 = *(const float4*)(dxp + t * 8);
            const float4 d1 = *(const float4*)(dxp + t * 8 + 4);
            const float dxi = dxp[t * 8 + i];
            const float dxj = dxp[t * 8 + j];

            const float a  = dxi * dxj;
            const float bb = S1h * dxj;
            const float coeff = fmaf(a, 0.16666666666666666f, bb + S2);

            S3[0] = fmaf(coeff, d0.x, S3[0]);
            S3[1] = fmaf(coeff, d0.y, S3[1]);
            S3[2] = fmaf(coeff, d0.z, S3[2]);
            S3[3] = fmaf(coeff, d0.w, S3[3]);
            S3[4] = fmaf(coeff, d1.x, S3[4]);
            S3[5] = fmaf(coeff, d1.y, S3[5]);
            S3[6] = fmaf(coeff, d1.z, S3[6]);
            S3[7] = fmaf(coeff, d1.w, S3[7]);

            S2  = fmaf(a, 0.5f, fmaf(2.f, bb, S2));
            S1h = fmaf(0.5f, dxi, S1h);
        }
    }

    float* __restrict__ op = g_part + (size_t)(batch * NSEG + seg) * SIGSZ;
    if (j == 0) op[i] = 2.f * S1h;
    op[8 + w] = S2;
    float4 s3a = make_float4(S3[0], S3[1], S3[2], S3[3]);
    float4 s3b = make_float4(S3[4], S3[5], S3[6], S3[7]);
    *(float4*)(op + 72 + w * 8)     = s3a;
    *(float4*)(op + 72 + w * 8 + 4) = s3b;
}

// ---------------------------------------------------------------------------
// Combine kernel: per batch, fold the 4 segment signatures left-to-right with
// Chen's identity:
//   S1 = A1 + B1
//   S2 = A2 + B2 + A1 (x) B1
//   S3 = A3 + B3 + A1 (x) B2 + A2 (x) B1
// Thread w = i*8+j holds A1[i], A2[i,j], A3[i,j,0..7].
// ---------------------------------------------------------------------------
__global__ __launch_bounds__(64) void combine_kernel(float* __restrict__ out) {
    const int w = threadIdx.x;
    const int i = w >> 3;
    const int j = w & 7;
    const int batch = blockIdx.x;

    const float* __restrict__ p0 = g_part + (size_t)batch * NSEG * SIGSZ;

    float A1i = p0[i];
    float A2  = p0[8 + w];
    float A3[8];
    {
        float4 a = *(const float4*)(p0 + 72 + w * 8);
        float4 b = *(const float4*)(p0 + 72 + w * 8 + 4);
        A3[0]=a.x; A3[1]=a.y; A3[2]=a.z; A3[3]=a.w;
        A3[4]=b.x; A3[5]=b.y; A3[6]=b.z; A3[7]=b.w;
    }

    #pragma unroll
    for (int s = 1; s < NSEG; s++) {
        const float* __restrict__ pbp = p0 + s * SIGSZ;
        const float B1i = pbp[i];
        const float B1j = pbp[j];
        float4 b1a = *(const float4*)(pbp);
        float4 b1b = *(const float4*)(pbp + 4);
        float4 b2a = *(const float4*)(pbp + 8 + j * 8);      // B2[j, 0..3]
        float4 b2b = *(const float4*)(pbp + 8 + j * 8 + 4);  // B2[j, 4..7]
        const float B2ij = pbp[8 + w];
        float4 b3a = *(const float4*)(pbp + 72 + w * 8);
        float4 b3b = *(const float4*)(pbp + 72 + w * 8 + 4);

        float b1v[8] = {b1a.x,b1a.y,b1a.z,b1a.w,b1b.x,b1b.y,b1b.z,b1b.w};
        float b2v[8] = {b2a.x,b2a.y,b2a.z,b2a.w,b2b.x,b2b.y,b2b.z,b2b.w};
        float b3v[8] = {b3a.x,b3a.y,b3a.z,b3a.w,b3b.x,b3b.y,b3b.z,b3b.w};

        #pragma unroll
        for (int k = 0; k < 8; k++) {
            // uses OLD A1i, A2
            A3[k] = fmaf(A1i, b2v[k], fmaf(A2, b1v[k], A3[k] + b3v[k]));
        }
        A2  = fmaf(A1i, B1j, A2 + B2ij);   // old A1i
        A1i = A1i + B1i;
    }

    float* __restrict__ ob = out + (size_t)batch * SIGSZ;
    if (j == 0) ob[i] = A1i;
    ob[8 + w] = A2;
    float4 s3a = make_float4(A3[0], A3[1], A3[2], A3[3]);
    float4 s3b = make_float4(A3[4], A3[5], A3[6], A3[7]);
    *(float4*)(ob + 72 + w * 8)     = s3a;
    *(float4*)(ob + 72 + w * 8 + 4) = s3b;
}

extern "C" void kernel_launch(void* const* d_in, const int* in_sizes, int n_in,
                              void* d_out, int out_size) {
    const float* path = (const float*)d_in[0];
    float* out = (float*)d_out;
    // 2048 (batch, segment) tasks, 2 tasks per 128-thread block
    seg_kernel<<<(NB * NSEG) / 2, 128>>>(path);
    combine_kernel<<<NB, 64>>>(out);
}